// round 10
// baseline (speedup 1.0000x reference)
#include <cuda_runtime.h>
#include <cuda_fp16.h>
#include <math.h>

// Problem constants
#define BATCH    64
#define IN_CAPS  2048
#define IN_DIM   16
#define NUM_CAPS 32
#define OUT_DIM  16
#define JD       512            // NUM_CAPS * OUT_DIM
#define NIC      32             // i-chunks per batch in iter kernels
#define IC       (IN_CAPS/NIC)  // 64 i's per block

// Scratch (device globals; allocation-free per harness rules)
__device__ __align__(16) __half g_uhat[(size_t)BATCH * IN_CAPS * JD];  // 128 MB, [b][i][j*16+d]
__device__ float g_spart[(size_t)BATCH * NIC * JD];  // 4 MB, d-major [b][ic][d*32+j]
__device__ float g_out0[(size_t)BATCH * JD];         // d-major [b][d*32+j]
__device__ float g_out1[(size_t)BATCH * JD];

// ---- packed f32x2 helpers (sm_103a) ---------------------------------------
static __device__ __forceinline__ unsigned long long pack2(float lo, float hi) {
    unsigned long long r;
    asm("mov.b64 %0, {%1, %2};" : "=l"(r) : "f"(lo), "f"(hi));
    return r;
}
#define FMA2(d, a, b, c) asm("fma.rn.f32x2 %0, %1, %2, %3;" : "=l"(d) : "l"(a), "l"(b), "l"(c))
#define MUL2(d, a, b)    asm("mul.rn.f32x2 %0, %1, %2;"     : "=l"(d) : "l"(a), "l"(b))

// ---------------------------------------------------------------------------
// K1: u_hat[b,i,jd] = sum_k W[i,jd,k] * x[b,i,k] -> fp16.
// One block per i (W read ONCE per block), 256 threads; thread owns the
// jd-PAIR (2t, 2t+1) with W packed as (W[jd0,k], W[jd1,k]) f32x2 pairs.
// Loop over all 64 b: 8 broadcast LDS.128 + 16 FMA2 + ONE coalesced STG.32
// (half2; warp stores 128B contiguous).
// ---------------------------------------------------------------------------
__global__ __launch_bounds__(256) void uhat_kernel(
    const float* __restrict__ x, const float* __restrict__ W)
{
    const int i   = blockIdx.x;
    const int t   = threadIdx.x;        // 0..255 = jd pair index
    const int jd0 = 2 * t;

    __shared__ unsigned long long xs[BATCH][16];   // (v,v) pairs, 8 KB

    {   // x loader: thread -> (b, float4 quarter)
        int b = t >> 2, q = t & 3;
        float4 v = *(const float4*)(x + ((size_t)b * IN_CAPS + i) * IN_DIM + 4 * q);
        xs[b][4 * q + 0] = pack2(v.x, v.x);
        xs[b][4 * q + 1] = pack2(v.y, v.y);
        xs[b][4 * q + 2] = pack2(v.z, v.z);
        xs[b][4 * q + 3] = pack2(v.w, v.w);
    }

    // W rows jd0, jd0+1 -> (w_jd0, w_jd1) pairs
    const float4* W0 = (const float4*)(W + ((size_t)i * JD + jd0) * IN_DIM);
    const float4* W1 = (const float4*)(W + ((size_t)i * JD + jd0 + 1) * IN_DIM);
    unsigned long long wp[16];
    #pragma unroll
    for (int q = 0; q < 4; q++) {
        float4 a = W0[q], b = W1[q];
        wp[4 * q + 0] = pack2(a.x, b.x);
        wp[4 * q + 1] = pack2(a.y, b.y);
        wp[4 * q + 2] = pack2(a.z, b.z);
        wp[4 * q + 3] = pack2(a.w, b.w);
    }

    __syncthreads();

    __half2* out = (__half2*)(g_uhat + (size_t)i * JD + jd0);
    #pragma unroll 4
    for (int b = 0; b < BATCH; b++) {
        const ulonglong2* ap = (const ulonglong2*)xs[b];   // broadcast reads
        ulonglong2 a0 = ap[0], a1 = ap[1], a2 = ap[2], a3 = ap[3];
        ulonglong2 a4 = ap[4], a5 = ap[5], a6 = ap[6], a7 = ap[7];
        unsigned long long acc;
        MUL2(acc, wp[0],  a0.x);
        FMA2(acc, wp[1],  a0.y, acc);
        FMA2(acc, wp[2],  a1.x, acc);
        FMA2(acc, wp[3],  a1.y, acc);
        FMA2(acc, wp[4],  a2.x, acc);
        FMA2(acc, wp[5],  a2.y, acc);
        FMA2(acc, wp[6],  a3.x, acc);
        FMA2(acc, wp[7],  a3.y, acc);
        FMA2(acc, wp[8],  a4.x, acc);
        FMA2(acc, wp[9],  a4.y, acc);
        FMA2(acc, wp[10], a5.x, acc);
        FMA2(acc, wp[11], a5.y, acc);
        FMA2(acc, wp[12], a6.x, acc);
        FMA2(acc, wp[13], a6.y, acc);
        FMA2(acc, wp[14], a7.x, acc);
        FMA2(acc, wp[15], a7.y, acc);
        float lo, hi;
        asm("mov.b64 {%0, %1}, %2;" : "=f"(lo), "=f"(hi) : "l"(acc));
        out[(size_t)b * IN_CAPS * (JD / 2)] = __floats2half2_rn(lo, hi);
    }
}

// ---------------------------------------------------------------------------
// iter-0 dedicated streaming sum: s0 partial = (1/32) * sum_i u_hat[b,i,:].
// No softmax -> flat uint4 streaming. Grid (NIC, BATCH), 256 threads:
// tt = t&63 owns jd-octet 8*tt, g = t>>6 strides i by 4. 16 independent
// LDG.128 per thread (deep MLP). Cross-group reduce in smem, write d-major.
// ---------------------------------------------------------------------------
__global__ __launch_bounds__(256) void iter0_kernel(int rev)
{
    const int b  = rev ? (BATCH - 1 - blockIdx.y) : blockIdx.y;
    const int ic = rev ? (NIC - 1 - blockIdx.x)   : blockIdx.x;
    const int t  = threadIdx.x;
    const int tt = t & 63;
    const int g  = t >> 6;
    const int i0 = ic * IC;

    const __half* base = g_uhat + ((size_t)b * IN_CAPS + i0) * JD + 8 * tt;

    float acc[8];
    #pragma unroll
    for (int e = 0; e < 8; e++) acc[e] = 0.f;

    #pragma unroll
    for (int s = 0; s < 16; s++) {
        uint4 r = *(const uint4*)(base + (size_t)(g + 4 * s) * JD);
        const __half2* h = (const __half2*)&r;
        #pragma unroll
        for (int e = 0; e < 4; e++) {
            float2 f = __half22float2(h[e]);
            acc[2 * e]     += f.x;
            acc[2 * e + 1] += f.y;
        }
    }

    // smem reduce over the 4 g-groups; layout [g][e][tt] (+pad) conflict-free
    __shared__ float red[4][8][66];
    #pragma unroll
    for (int e = 0; e < 8; e++) red[g][e][tt] = acc[e];
    __syncthreads();

    float* sp = g_spart + ((size_t)b * NIC + ic) * JD;
    #pragma unroll
    for (int h = 0; h < 2; h++) {
        int jd = t + 256 * h;
        float s = red[0][jd & 7][jd >> 3] + red[1][jd & 7][jd >> 3]
                + red[2][jd & 7][jd >> 3] + red[3][jd & 7][jd >> 3];
        sp[(jd & 15) * 32 + (jd >> 4)] = s * (1.0f / NUM_CAPS);
    }
}

// ---------------------------------------------------------------------------
// Fused routing iteration (iters 1/2; proven R7 config) + L2 ping-pong.
// Lane = j; lane loads u_hat[b,i,lane,0:15] (32B). Agreement dot in half2;
// softmax over j without max subtraction (exact: shift-invariant, |a| small).
// iter1 logits = <u,out0>; iter2 logits = <u,out0+out1>.
// ---------------------------------------------------------------------------
__global__ __launch_bounds__(256, 4) void iter_kernel(int iter, int rev)
{
    const int b    = rev ? (BATCH - 1 - blockIdx.y) : blockIdx.y;
    const int ic   = rev ? (NIC - 1 - blockIdx.x)   : blockIdx.x;
    const int t    = threadIdx.x;
    const int w    = t >> 5;
    const int lane = t & 31;            // = j
    const int i0   = ic * IC;

    __half2 vout2[8];
    #pragma unroll
    for (int d2 = 0; d2 < 8; d2++) {
        float f0 = g_out0[(size_t)b * JD + (2 * d2)     * 32 + lane];
        float f1 = g_out0[(size_t)b * JD + (2 * d2 + 1) * 32 + lane];
        if (iter == 2) {
            f0 += g_out1[(size_t)b * JD + (2 * d2)     * 32 + lane];
            f1 += g_out1[(size_t)b * JD + (2 * d2 + 1) * 32 + lane];
        }
        vout2[d2] = __floats2half2_rn(f0, f1);
    }

    float acc[16];
    #pragma unroll
    for (int d = 0; d < 16; d++) acc[d] = 0.f;

    const __half* uhbase = g_uhat + ((size_t)b * IN_CAPS + i0) * JD + lane * 16;

    #pragma unroll
    for (int step = 0; step < 4; step++) {
        const int iiA = w + step * 16;
        const int iiB = iiA + 8;
        const uint4* pA = (const uint4*)(uhbase + (size_t)iiA * JD);
        const uint4* pB = (const uint4*)(uhbase + (size_t)iiB * JD);
        uint4 ra0 = pA[0], ra1 = pA[1];     // i = iiA : d 0..7, 8..15
        uint4 rb0 = pB[0], rb1 = pB[1];     // i = iiB

        // Agreement dots for both i's (independent chains, ILP)
        __half2 hA = __hmul2(((const __half2*)&ra0)[0], vout2[0]);
        __half2 hB = __hmul2(((const __half2*)&rb0)[0], vout2[0]);
        #pragma unroll
        for (int d2 = 1; d2 < 4; d2++) {
            hA = __hfma2(((const __half2*)&ra0)[d2], vout2[d2], hA);
            hB = __hfma2(((const __half2*)&rb0)[d2], vout2[d2], hB);
        }
        #pragma unroll
        for (int d2 = 0; d2 < 4; d2++) {
            hA = __hfma2(((const __half2*)&ra1)[d2], vout2[4 + d2], hA);
            hB = __hfma2(((const __half2*)&rb1)[d2], vout2[4 + d2], hB);
        }
        float eA = __expf(__low2float(hA) + __high2float(hA));
        float eB = __expf(__low2float(hB) + __high2float(hB));

        float sA = eA, sB = eB;   // interleaved butterflies (no max pass)
        #pragma unroll
        for (int o = 16; o; o >>= 1) {
            sA += __shfl_xor_sync(0xffffffffu, sA, o);
            sB += __shfl_xor_sync(0xffffffffu, sB, o);
        }
        float cA = eA / sA;
        float cB = eB / sB;

        #pragma unroll
        for (int d2 = 0; d2 < 4; d2++) {
            float2 f = __half22float2(((const __half2*)&ra0)[d2]);
            acc[2 * d2]     = fmaf(cA, f.x, acc[2 * d2]);
            acc[2 * d2 + 1] = fmaf(cA, f.y, acc[2 * d2 + 1]);
            float2 g = __half22float2(((const __half2*)&ra1)[d2]);
            acc[8 + 2 * d2]     = fmaf(cA, g.x, acc[8 + 2 * d2]);
            acc[8 + 2 * d2 + 1] = fmaf(cA, g.y, acc[8 + 2 * d2 + 1]);
        }
        #pragma unroll
        for (int d2 = 0; d2 < 4; d2++) {
            float2 f = __half22float2(((const __half2*)&rb0)[d2]);
            acc[2 * d2]     = fmaf(cB, f.x, acc[2 * d2]);
            acc[2 * d2 + 1] = fmaf(cB, f.y, acc[2 * d2 + 1]);
            float2 g = __half22float2(((const __half2*)&rb1)[d2]);
            acc[8 + 2 * d2]     = fmaf(cB, g.x, acc[8 + 2 * d2]);
            acc[8 + 2 * d2 + 1] = fmaf(cB, g.y, acc[8 + 2 * d2 + 1]);
        }
    }

    // Cross-warp reduce (d-major in smem: conflict-free)
    __shared__ float red[8][JD];
    #pragma unroll
    for (int d = 0; d < 16; d++) red[w][d * 32 + lane] = acc[d];
    __syncthreads();

    float s1 = 0.f, s2 = 0.f;
    #pragma unroll
    for (int ww = 0; ww < 8; ww++) {
        s1 += red[ww][t];
        s2 += red[ww][t + 256];
    }
    float* sp = g_spart + ((size_t)b * NIC + ic) * JD;
    sp[t]       = s1;
    sp[t + 256] = s2;
}

// ---------------------------------------------------------------------------
// Reduce partials over NIC chunks + squash. d-major positions: t = d*32 + j.
// which: 0 -> g_out0, 1 -> g_out1, 2 -> dout (permuted to [b][j][d]).
// ---------------------------------------------------------------------------
__global__ __launch_bounds__(512) void squash_kernel(int which, float* __restrict__ dout)
{
    const int b = blockIdx.x;
    const int t = threadIdx.x;

    const float* sp = g_spart + (size_t)b * NIC * JD + t;
    float s = 0.f;
    #pragma unroll
    for (int p = 0; p < NIC; p++) s += sp[(size_t)p * JD];

    __shared__ float s2s[NUM_CAPS];
    if (t < NUM_CAPS) s2s[t] = 0.f;
    __syncthreads();
    atomicAdd(&s2s[t & 31], s * s);
    __syncthreads();

    float s2 = s2s[t & 31];
    float scale = s2 / ((1.0f + s2) * sqrtf(s2 + 1e-7f));
    float v = s * scale;

    if (which == 2)      dout[(size_t)b * JD + (t & 31) * 16 + (t >> 5)] = v;
    else if (which == 0) g_out0[(size_t)b * JD + t] = v;
    else                 g_out1[(size_t)b * JD + t] = v;
}

// ---------------------------------------------------------------------------
extern "C" void kernel_launch(void* const* d_in, const int* in_sizes, int n_in,
                              void* d_out, int out_size)
{
    const float* x = (const float*)d_in[0];
    const float* W = (const float*)d_in[1];
    if (in_sizes[0] == (int)((size_t)IN_CAPS * NUM_CAPS * IN_DIM * OUT_DIM)) {
        const float* tmp = x; x = W; W = tmp;
    }
    float* out = (float*)d_out;

    dim3 ig(NIC, BATCH);

    // L2 ping-pong: uhat ascending-i; alternate direction each pass so every
    // pass starts on the L2-resident tail of the previous one.
    uhat_kernel<<<IN_CAPS, 256>>>(x, W);

    iter0_kernel<<<ig, 256>>>(1);            // reverse
    squash_kernel<<<BATCH, 512>>>(0, out);   // -> g_out0

    iter_kernel<<<ig, 256>>>(1, 0);          // forward
    squash_kernel<<<BATCH, 512>>>(1, out);   // -> g_out1

    iter_kernel<<<ig, 256>>>(2, 1);          // reverse
    squash_kernel<<<BATCH, 512>>>(2, out);   // -> dout
}

// round 11
// speedup vs baseline: 1.0259x; 1.0259x over previous
#include <cuda_runtime.h>
#include <cuda_fp16.h>
#include <math.h>

// Problem constants
#define BATCH    64
#define IN_CAPS  2048
#define IN_DIM   16
#define NUM_CAPS 32
#define OUT_DIM  16
#define JD       512            // NUM_CAPS * OUT_DIM
#define NIC      32             // i-chunks per batch in iter kernel
#define IC       (IN_CAPS/NIC)  // 64 i's per block

// Scratch (device globals; allocation-free per harness rules)
__device__ __align__(16) __half g_uhat[(size_t)BATCH * IN_CAPS * JD];  // 128 MB, [b][i][j*16+d]
__device__ float g_spart[(size_t)BATCH * NIC * JD];  // 4 MB, d-major [b][ic][d*32+j]
__device__ float g_out0[(size_t)BATCH * JD];         // d-major [b][d*32+j]
__device__ float g_out1[(size_t)BATCH * JD];

// ---- packed f32x2 helpers (sm_103a) ---------------------------------------
static __device__ __forceinline__ unsigned long long pack2(float lo, float hi) {
    unsigned long long r;
    asm("mov.b64 %0, {%1, %2};" : "=l"(r) : "f"(lo), "f"(hi));
    return r;
}
#define FMA2(d, a, b, c) asm("fma.rn.f32x2 %0, %1, %2, %3;" : "=l"(d) : "l"(a), "l"(b), "l"(c))
#define MUL2(d, a, b)    asm("mul.rn.f32x2 %0, %1, %2;"     : "=l"(d) : "l"(a), "l"(b))

// ---------------------------------------------------------------------------
// K1 (proven R9 config): u_hat[b,i,jd] = sum_k W[i,jd,k] * x[b,i,k].
// One block per i, 512 threads (t = jd). x staged in smem pre-packed as
// (b, b+1) f32x2 pairs; W row held in regs as (w,w) pairs. fma.rn.f32x2
// computes 2 batches per 16 packed FMAs. Coalesced W float4 reads.
// ---------------------------------------------------------------------------
__global__ __launch_bounds__(512) void uhat_kernel(
    const float* __restrict__ x, const float* __restrict__ W)
{
    const int i = blockIdx.x;
    const int t = threadIdx.x;          // 0..511

    __shared__ unsigned long long xp[32][16];   // 32 b-pairs x 16 k

    {
        int p = t >> 4, k = t & 15;     // 512 threads cover all 32*16
        float lo = x[((size_t)(2 * p)     * IN_CAPS + i) * IN_DIM + k];
        float hi = x[((size_t)(2 * p + 1) * IN_CAPS + i) * IN_DIM + k];
        xp[p][k] = pack2(lo, hi);
    }

    const float4* Wr = (const float4*)(W + ((size_t)i * JD + t) * IN_DIM);
    float4 w0 = Wr[0], w1 = Wr[1], w2 = Wr[2], w3 = Wr[3];
    unsigned long long wp[16];
    wp[0]  = pack2(w0.x, w0.x); wp[1]  = pack2(w0.y, w0.y);
    wp[2]  = pack2(w0.z, w0.z); wp[3]  = pack2(w0.w, w0.w);
    wp[4]  = pack2(w1.x, w1.x); wp[5]  = pack2(w1.y, w1.y);
    wp[6]  = pack2(w1.z, w1.z); wp[7]  = pack2(w1.w, w1.w);
    wp[8]  = pack2(w2.x, w2.x); wp[9]  = pack2(w2.y, w2.y);
    wp[10] = pack2(w2.z, w2.z); wp[11] = pack2(w2.w, w2.w);
    wp[12] = pack2(w3.x, w3.x); wp[13] = pack2(w3.y, w3.y);
    wp[14] = pack2(w3.z, w3.z); wp[15] = pack2(w3.w, w3.w);

    __syncthreads();

    __half* out = g_uhat + (size_t)i * JD + t;
    #pragma unroll 4
    for (int p = 0; p < 32; p++) {
        const ulonglong2* ap = (const ulonglong2*)xp[p];
        ulonglong2 a0 = ap[0], a1 = ap[1], a2 = ap[2], a3 = ap[3];
        ulonglong2 a4 = ap[4], a5 = ap[5], a6 = ap[6], a7 = ap[7];
        unsigned long long acc;
        MUL2(acc, wp[0],  a0.x);
        FMA2(acc, wp[1],  a0.y, acc);
        FMA2(acc, wp[2],  a1.x, acc);
        FMA2(acc, wp[3],  a1.y, acc);
        FMA2(acc, wp[4],  a2.x, acc);
        FMA2(acc, wp[5],  a2.y, acc);
        FMA2(acc, wp[6],  a3.x, acc);
        FMA2(acc, wp[7],  a3.y, acc);
        FMA2(acc, wp[8],  a4.x, acc);
        FMA2(acc, wp[9],  a4.y, acc);
        FMA2(acc, wp[10], a5.x, acc);
        FMA2(acc, wp[11], a5.y, acc);
        FMA2(acc, wp[12], a6.x, acc);
        FMA2(acc, wp[13], a6.y, acc);
        FMA2(acc, wp[14], a7.x, acc);
        FMA2(acc, wp[15], a7.y, acc);
        float lo, hi;
        asm("mov.b64 {%0, %1}, %2;" : "=f"(lo), "=f"(hi) : "l"(acc));
        out[(size_t)(2 * p)     * IN_CAPS * JD] = __float2half_rn(lo);
        out[(size_t)(2 * p + 1) * IN_CAPS * JD] = __float2half_rn(hi);
    }
}

// ---------------------------------------------------------------------------
// Fused routing iteration + L2 ping-pong + SOFTWARE PIPELINING:
// the next step's 4 LDG.128 are issued before processing the current step,
// doubling per-warp MLP (8 outstanding LDG.128) to cover DRAM latency.
// 3 blocks/SM (regs ~80). Lane = j; agreement dot in half2; softmax without
// max subtraction (exact). iter1 logits = <u,out0>; iter2 = <u,out0+out1>.
// ---------------------------------------------------------------------------
__global__ __launch_bounds__(256, 3) void iter_kernel(int iter, int rev)
{
    const int b    = rev ? (BATCH - 1 - blockIdx.y) : blockIdx.y;
    const int ic   = rev ? (NIC - 1 - blockIdx.x)   : blockIdx.x;
    const int t    = threadIdx.x;
    const int w    = t >> 5;
    const int lane = t & 31;            // = j
    const int i0   = ic * IC;

    __half2 vout2[8];
    if (iter > 0) {
        #pragma unroll
        for (int d2 = 0; d2 < 8; d2++) {
            float f0 = g_out0[(size_t)b * JD + (2 * d2)     * 32 + lane];
            float f1 = g_out0[(size_t)b * JD + (2 * d2 + 1) * 32 + lane];
            if (iter == 2) {
                f0 += g_out1[(size_t)b * JD + (2 * d2)     * 32 + lane];
                f1 += g_out1[(size_t)b * JD + (2 * d2 + 1) * 32 + lane];
            }
            vout2[d2] = __floats2half2_rn(f0, f1);
        }
    }

    float acc[16];
    #pragma unroll
    for (int d = 0; d < 16; d++) acc[d] = 0.f;

    const __half* uhbase = g_uhat + ((size_t)b * IN_CAPS + i0) * JD + lane * 16;

    // prologue: loads for step 0
    uint4 ra0, ra1, rb0, rb1;
    {
        const uint4* pA = (const uint4*)(uhbase + (size_t)w * JD);
        const uint4* pB = (const uint4*)(uhbase + (size_t)(w + 8) * JD);
        ra0 = pA[0]; ra1 = pA[1];
        rb0 = pB[0]; rb1 = pB[1];
    }

    #pragma unroll
    for (int step = 0; step < 4; step++) {
        // prefetch step+1 BEFORE consuming the current data
        uint4 na0, na1, nb0, nb1;
        if (step < 3) {
            const int iiA = w + (step + 1) * 16;
            const uint4* pA = (const uint4*)(uhbase + (size_t)iiA * JD);
            const uint4* pB = (const uint4*)(uhbase + (size_t)(iiA + 8) * JD);
            na0 = pA[0]; na1 = pA[1];
            nb0 = pB[0]; nb1 = pB[1];
        }

        if (iter == 0) {
            #pragma unroll
            for (int half_sel = 0; half_sel < 2; half_sel++) {
                const __half2* v2 = (const __half2*)(half_sel ? &rb0 : &ra0);
                const __half2* v3 = (const __half2*)(half_sel ? &rb1 : &ra1);
                #pragma unroll
                for (int d2 = 0; d2 < 4; d2++) {
                    float2 f = __half22float2(v2[d2]);
                    acc[2 * d2]     += f.x;
                    acc[2 * d2 + 1] += f.y;
                    float2 g = __half22float2(v3[d2]);
                    acc[8 + 2 * d2]     += g.x;
                    acc[8 + 2 * d2 + 1] += g.y;
                }
            }
        } else {
            // Agreement dots for both i's (independent chains, ILP)
            __half2 hA = __hmul2(((const __half2*)&ra0)[0], vout2[0]);
            __half2 hB = __hmul2(((const __half2*)&rb0)[0], vout2[0]);
            #pragma unroll
            for (int d2 = 1; d2 < 4; d2++) {
                hA = __hfma2(((const __half2*)&ra0)[d2], vout2[d2], hA);
                hB = __hfma2(((const __half2*)&rb0)[d2], vout2[d2], hB);
            }
            #pragma unroll
            for (int d2 = 0; d2 < 4; d2++) {
                hA = __hfma2(((const __half2*)&ra1)[d2], vout2[4 + d2], hA);
                hB = __hfma2(((const __half2*)&rb1)[d2], vout2[4 + d2], hB);
            }
            float eA = __expf(__low2float(hA) + __high2float(hA));
            float eB = __expf(__low2float(hB) + __high2float(hB));

            float sA = eA, sB = eB;   // interleaved butterflies (no max pass)
            #pragma unroll
            for (int o = 16; o; o >>= 1) {
                sA += __shfl_xor_sync(0xffffffffu, sA, o);
                sB += __shfl_xor_sync(0xffffffffu, sB, o);
            }
            float cA = eA / sA;
            float cB = eB / sB;

            #pragma unroll
            for (int d2 = 0; d2 < 4; d2++) {
                float2 f = __half22float2(((const __half2*)&ra0)[d2]);
                acc[2 * d2]     = fmaf(cA, f.x, acc[2 * d2]);
                acc[2 * d2 + 1] = fmaf(cA, f.y, acc[2 * d2 + 1]);
                float2 g = __half22float2(((const __half2*)&ra1)[d2]);
                acc[8 + 2 * d2]     = fmaf(cA, g.x, acc[8 + 2 * d2]);
                acc[8 + 2 * d2 + 1] = fmaf(cA, g.y, acc[8 + 2 * d2 + 1]);
            }
            #pragma unroll
            for (int d2 = 0; d2 < 4; d2++) {
                float2 f = __half22float2(((const __half2*)&rb0)[d2]);
                acc[2 * d2]     = fmaf(cB, f.x, acc[2 * d2]);
                acc[2 * d2 + 1] = fmaf(cB, f.y, acc[2 * d2 + 1]);
                float2 g = __half22float2(((const __half2*)&rb1)[d2]);
                acc[8 + 2 * d2]     = fmaf(cB, g.x, acc[8 + 2 * d2]);
                acc[8 + 2 * d2 + 1] = fmaf(cB, g.y, acc[8 + 2 * d2 + 1]);
            }
        }

        if (step < 3) {
            ra0 = na0; ra1 = na1;
            rb0 = nb0; rb1 = nb1;
        }
    }

    if (iter == 0) {
        #pragma unroll
        for (int d = 0; d < 16; d++) acc[d] *= (1.0f / NUM_CAPS);
    }

    // Cross-warp reduce (d-major in smem: conflict-free)
    __shared__ float red[8][JD];
    #pragma unroll
    for (int d = 0; d < 16; d++) red[w][d * 32 + lane] = acc[d];
    __syncthreads();

    float s1 = 0.f, s2 = 0.f;
    #pragma unroll
    for (int ww = 0; ww < 8; ww++) {
        s1 += red[ww][t];
        s2 += red[ww][t + 256];
    }
    float* sp = g_spart + ((size_t)b * NIC + ic) * JD;
    sp[t]       = s1;
    sp[t + 256] = s2;
}

// ---------------------------------------------------------------------------
// Reduce partials over NIC chunks + squash. d-major positions: t = d*32 + j.
// which: 0 -> g_out0, 1 -> g_out1, 2 -> dout (permuted to [b][j][d]).
// ---------------------------------------------------------------------------
__global__ __launch_bounds__(512) void squash_kernel(int which, float* __restrict__ dout)
{
    const int b = blockIdx.x;
    const int t = threadIdx.x;

    const float* sp = g_spart + (size_t)b * NIC * JD + t;
    float s = 0.f;
    #pragma unroll
    for (int p = 0; p < NIC; p++) s += sp[(size_t)p * JD];

    __shared__ float s2s[NUM_CAPS];
    if (t < NUM_CAPS) s2s[t] = 0.f;
    __syncthreads();
    atomicAdd(&s2s[t & 31], s * s);
    __syncthreads();

    float s2 = s2s[t & 31];
    float scale = s2 / ((1.0f + s2) * sqrtf(s2 + 1e-7f));
    float v = s * scale;

    if (which == 2)      dout[(size_t)b * JD + (t & 31) * 16 + (t >> 5)] = v;
    else if (which == 0) g_out0[(size_t)b * JD + t] = v;
    else                 g_out1[(size_t)b * JD + t] = v;
}

// ---------------------------------------------------------------------------
extern "C" void kernel_launch(void* const* d_in, const int* in_sizes, int n_in,
                              void* d_out, int out_size)
{
    const float* x = (const float*)d_in[0];
    const float* W = (const float*)d_in[1];
    if (in_sizes[0] == (int)((size_t)IN_CAPS * NUM_CAPS * IN_DIM * OUT_DIM)) {
        const float* tmp = x; x = W; W = tmp;
    }
    float* out = (float*)d_out;

    dim3 ig(NIC, BATCH);

    // L2 ping-pong: uhat ascending-i; alternate direction each pass so every
    // pass starts on the L2-resident tail of the previous one.
    uhat_kernel<<<IN_CAPS, 512>>>(x, W);

    iter_kernel<<<ig, 256>>>(0, 1);          // reverse
    squash_kernel<<<BATCH, 512>>>(0, out);   // -> g_out0

    iter_kernel<<<ig, 256>>>(1, 0);          // forward
    squash_kernel<<<BATCH, 512>>>(1, out);   // -> g_out1

    iter_kernel<<<ig, 256>>>(2, 1);          // reverse
    squash_kernel<<<BATCH, 512>>>(2, out);   // -> dout
}

// round 12
// speedup vs baseline: 1.0368x; 1.0106x over previous
#include <cuda_runtime.h>
#include <cuda_fp16.h>
#include <math.h>

// Problem constants
#define BATCH    64
#define IN_CAPS  2048
#define IN_DIM   16
#define NUM_CAPS 32
#define OUT_DIM  16
#define JD       512            // NUM_CAPS * OUT_DIM
#define NIC      32             // i-chunks per batch in iter kernel
#define IC       (IN_CAPS/NIC)  // 64 i's per block

// Scratch (device globals; allocation-free per harness rules)
__device__ __align__(16) __half g_uhat[(size_t)BATCH * IN_CAPS * JD];  // 128 MB, [b][i][j*16+d]
__device__ float g_spart[(size_t)BATCH * NIC * JD];  // 4 MB, d-major [b][ic][d*32+j]
__device__ float g_out0[(size_t)BATCH * JD];         // d-major [b][d*32+j]
__device__ float g_out1[(size_t)BATCH * JD];

// ---- packed f32x2 helpers (sm_103a) ---------------------------------------
static __device__ __forceinline__ unsigned long long pack2(float lo, float hi) {
    unsigned long long r;
    asm("mov.b64 %0, {%1, %2};" : "=l"(r) : "f"(lo), "f"(hi));
    return r;
}
#define FMA2(d, a, b, c) asm("fma.rn.f32x2 %0, %1, %2, %3;" : "=l"(d) : "l"(a), "l"(b), "l"(c))
#define MUL2(d, a, b)    asm("mul.rn.f32x2 %0, %1, %2;"     : "=l"(d) : "l"(a), "l"(b))

// ---------------------------------------------------------------------------
// K1 (proven R9 config): u_hat[b,i,jd] = sum_k W[i,jd,k] * x[b,i,k].
// One block per i, 512 threads (t = jd). x staged in smem pre-packed as
// (b, b+1) f32x2 pairs; W row held in regs as (w,w) pairs. fma.rn.f32x2
// computes 2 batches per 16 packed FMAs. Coalesced W float4 reads.
// ---------------------------------------------------------------------------
__global__ __launch_bounds__(512) void uhat_kernel(
    const float* __restrict__ x, const float* __restrict__ W)
{
    const int i = blockIdx.x;
    const int t = threadIdx.x;          // 0..511

    __shared__ unsigned long long xp[32][16];   // 32 b-pairs x 16 k

    {
        int p = t >> 4, k = t & 15;     // 512 threads cover all 32*16
        float lo = x[((size_t)(2 * p)     * IN_CAPS + i) * IN_DIM + k];
        float hi = x[((size_t)(2 * p + 1) * IN_CAPS + i) * IN_DIM + k];
        xp[p][k] = pack2(lo, hi);
    }

    const float4* Wr = (const float4*)(W + ((size_t)i * JD + t) * IN_DIM);
    float4 w0 = Wr[0], w1 = Wr[1], w2 = Wr[2], w3 = Wr[3];
    unsigned long long wp[16];
    wp[0]  = pack2(w0.x, w0.x); wp[1]  = pack2(w0.y, w0.y);
    wp[2]  = pack2(w0.z, w0.z); wp[3]  = pack2(w0.w, w0.w);
    wp[4]  = pack2(w1.x, w1.x); wp[5]  = pack2(w1.y, w1.y);
    wp[6]  = pack2(w1.z, w1.z); wp[7]  = pack2(w1.w, w1.w);
    wp[8]  = pack2(w2.x, w2.x); wp[9]  = pack2(w2.y, w2.y);
    wp[10] = pack2(w2.z, w2.z); wp[11] = pack2(w2.w, w2.w);
    wp[12] = pack2(w3.x, w3.x); wp[13] = pack2(w3.y, w3.y);
    wp[14] = pack2(w3.z, w3.z); wp[15] = pack2(w3.w, w3.w);

    __syncthreads();

    __half* out = g_uhat + (size_t)i * JD + t;
    #pragma unroll 4
    for (int p = 0; p < 32; p++) {
        const ulonglong2* ap = (const ulonglong2*)xp[p];
        ulonglong2 a0 = ap[0], a1 = ap[1], a2 = ap[2], a3 = ap[3];
        ulonglong2 a4 = ap[4], a5 = ap[5], a6 = ap[6], a7 = ap[7];
        unsigned long long acc;
        MUL2(acc, wp[0],  a0.x);
        FMA2(acc, wp[1],  a0.y, acc);
        FMA2(acc, wp[2],  a1.x, acc);
        FMA2(acc, wp[3],  a1.y, acc);
        FMA2(acc, wp[4],  a2.x, acc);
        FMA2(acc, wp[5],  a2.y, acc);
        FMA2(acc, wp[6],  a3.x, acc);
        FMA2(acc, wp[7],  a3.y, acc);
        FMA2(acc, wp[8],  a4.x, acc);
        FMA2(acc, wp[9],  a4.y, acc);
        FMA2(acc, wp[10], a5.x, acc);
        FMA2(acc, wp[11], a5.y, acc);
        FMA2(acc, wp[12], a6.x, acc);
        FMA2(acc, wp[13], a6.y, acc);
        FMA2(acc, wp[14], a7.x, acc);
        FMA2(acc, wp[15], a7.y, acc);
        float lo, hi;
        asm("mov.b64 {%0, %1}, %2;" : "=f"(lo), "=f"(hi) : "l"(acc));
        out[(size_t)(2 * p)     * IN_CAPS * JD] = __float2half_rn(lo);
        out[(size_t)(2 * p + 1) * IN_CAPS * JD] = __float2half_rn(hi);
    }
}

// ---------------------------------------------------------------------------
// Fused routing iteration + L2 ping-pong + SOFTWARE PIPELINING:
// the next step's 4 LDG.128 are issued before processing the current step,
// doubling per-warp MLP (8 outstanding LDG.128) to cover DRAM latency.
// 3 blocks/SM (regs ~80). Lane = j; agreement dot in half2; softmax without
// max subtraction (exact). iter1 logits = <u,out0>; iter2 = <u,out0+out1>.
// ---------------------------------------------------------------------------
__global__ __launch_bounds__(256, 3) void iter_kernel(int iter, int rev)
{
    const int b    = rev ? (BATCH - 1 - blockIdx.y) : blockIdx.y;
    const int ic   = rev ? (NIC - 1 - blockIdx.x)   : blockIdx.x;
    const int t    = threadIdx.x;
    const int w    = t >> 5;
    const int lane = t & 31;            // = j
    const int i0   = ic * IC;

    __half2 vout2[8];
    if (iter > 0) {
        #pragma unroll
        for (int d2 = 0; d2 < 8; d2++) {
            float f0 = g_out0[(size_t)b * JD + (2 * d2)     * 32 + lane];
            float f1 = g_out0[(size_t)b * JD + (2 * d2 + 1) * 32 + lane];
            if (iter == 2) {
                f0 += g_out1[(size_t)b * JD + (2 * d2)     * 32 + lane];
                f1 += g_out1[(size_t)b * JD + (2 * d2 + 1) * 32 + lane];
            }
            vout2[d2] = __floats2half2_rn(f0, f1);
        }
    }

    float acc[16];
    #pragma unroll
    for (int d = 0; d < 16; d++) acc[d] = 0.f;

    const __half* uhbase = g_uhat + ((size_t)b * IN_CAPS + i0) * JD + lane * 16;

    // prologue: loads for step 0
    uint4 ra0, ra1, rb0, rb1;
    {
        const uint4* pA = (const uint4*)(uhbase + (size_t)w * JD);
        const uint4* pB = (const uint4*)(uhbase + (size_t)(w + 8) * JD);
        ra0 = pA[0]; ra1 = pA[1];
        rb0 = pB[0]; rb1 = pB[1];
    }

    #pragma unroll
    for (int step = 0; step < 4; step++) {
        // prefetch step+1 BEFORE consuming the current data
        uint4 na0, na1, nb0, nb1;
        if (step < 3) {
            const int iiA = w + (step + 1) * 16;
            const uint4* pA = (const uint4*)(uhbase + (size_t)iiA * JD);
            const uint4* pB = (const uint4*)(uhbase + (size_t)(iiA + 8) * JD);
            na0 = pA[0]; na1 = pA[1];
            nb0 = pB[0]; nb1 = pB[1];
        }

        if (iter == 0) {
            #pragma unroll
            for (int half_sel = 0; half_sel < 2; half_sel++) {
                const __half2* v2 = (const __half2*)(half_sel ? &rb0 : &ra0);
                const __half2* v3 = (const __half2*)(half_sel ? &rb1 : &ra1);
                #pragma unroll
                for (int d2 = 0; d2 < 4; d2++) {
                    float2 f = __half22float2(v2[d2]);
                    acc[2 * d2]     += f.x;
                    acc[2 * d2 + 1] += f.y;
                    float2 g = __half22float2(v3[d2]);
                    acc[8 + 2 * d2]     += g.x;
                    acc[8 + 2 * d2 + 1] += g.y;
                }
            }
        } else {
            // Agreement dots for both i's (independent chains, ILP)
            __half2 hA = __hmul2(((const __half2*)&ra0)[0], vout2[0]);
            __half2 hB = __hmul2(((const __half2*)&rb0)[0], vout2[0]);
            #pragma unroll
            for (int d2 = 1; d2 < 4; d2++) {
                hA = __hfma2(((const __half2*)&ra0)[d2], vout2[d2], hA);
                hB = __hfma2(((const __half2*)&rb0)[d2], vout2[d2], hB);
            }
            #pragma unroll
            for (int d2 = 0; d2 < 4; d2++) {
                hA = __hfma2(((const __half2*)&ra1)[d2], vout2[4 + d2], hA);
                hB = __hfma2(((const __half2*)&rb1)[d2], vout2[4 + d2], hB);
            }
            float eA = __expf(__low2float(hA) + __high2float(hA));
            float eB = __expf(__low2float(hB) + __high2float(hB));

            float sA = eA, sB = eB;   // interleaved butterflies (no max pass)
            #pragma unroll
            for (int o = 16; o; o >>= 1) {
                sA += __shfl_xor_sync(0xffffffffu, sA, o);
                sB += __shfl_xor_sync(0xffffffffu, sB, o);
            }
            float cA = eA / sA;
            float cB = eB / sB;

            #pragma unroll
            for (int d2 = 0; d2 < 4; d2++) {
                float2 f = __half22float2(((const __half2*)&ra0)[d2]);
                acc[2 * d2]     = fmaf(cA, f.x, acc[2 * d2]);
                acc[2 * d2 + 1] = fmaf(cA, f.y, acc[2 * d2 + 1]);
                float2 g = __half22float2(((const __half2*)&ra1)[d2]);
                acc[8 + 2 * d2]     = fmaf(cA, g.x, acc[8 + 2 * d2]);
                acc[8 + 2 * d2 + 1] = fmaf(cA, g.y, acc[8 + 2 * d2 + 1]);
            }
            #pragma unroll
            for (int d2 = 0; d2 < 4; d2++) {
                float2 f = __half22float2(((const __half2*)&rb0)[d2]);
                acc[2 * d2]     = fmaf(cB, f.x, acc[2 * d2]);
                acc[2 * d2 + 1] = fmaf(cB, f.y, acc[2 * d2 + 1]);
                float2 g = __half22float2(((const __half2*)&rb1)[d2]);
                acc[8 + 2 * d2]     = fmaf(cB, g.x, acc[8 + 2 * d2]);
                acc[8 + 2 * d2 + 1] = fmaf(cB, g.y, acc[8 + 2 * d2 + 1]);
            }
        }

        if (step < 3) {
            ra0 = na0; ra1 = na1;
            rb0 = nb0; rb1 = nb1;
        }
    }

    if (iter == 0) {
        #pragma unroll
        for (int d = 0; d < 16; d++) acc[d] *= (1.0f / NUM_CAPS);
    }

    // Cross-warp reduce (d-major in smem: conflict-free)
    __shared__ float red[8][JD];
    #pragma unroll
    for (int d = 0; d < 16; d++) red[w][d * 32 + lane] = acc[d];
    __syncthreads();

    float s1 = 0.f, s2 = 0.f;
    #pragma unroll
    for (int ww = 0; ww < 8; ww++) {
        s1 += red[ww][t];
        s2 += red[ww][t + 256];
    }
    float* sp = g_spart + ((size_t)b * NIC + ic) * JD;
    sp[t]       = s1;
    sp[t + 256] = s2;
}

// ---------------------------------------------------------------------------
// Reduce partials over NIC chunks + squash. d-major positions: t = d*32 + j.
// which: 0 -> g_out0, 1 -> g_out1, 2 -> dout (permuted to [b][j][d]).
// ---------------------------------------------------------------------------
__global__ __launch_bounds__(512) void squash_kernel(int which, float* __restrict__ dout)
{
    const int b = blockIdx.x;
    const int t = threadIdx.x;

    const float* sp = g_spart + (size_t)b * NIC * JD + t;
    float s = 0.f;
    #pragma unroll
    for (int p = 0; p < NIC; p++) s += sp[(size_t)p * JD];

    __shared__ float s2s[NUM_CAPS];
    if (t < NUM_CAPS) s2s[t] = 0.f;
    __syncthreads();
    atomicAdd(&s2s[t & 31], s * s);
    __syncthreads();

    float s2 = s2s[t & 31];
    float scale = s2 / ((1.0f + s2) * sqrtf(s2 + 1e-7f));
    float v = s * scale;

    if (which == 2)      dout[(size_t)b * JD + (t & 31) * 16 + (t >> 5)] = v;
    else if (which == 0) g_out0[(size_t)b * JD + t] = v;
    else                 g_out1[(size_t)b * JD + t] = v;
}

// ---------------------------------------------------------------------------
extern "C" void kernel_launch(void* const* d_in, const int* in_sizes, int n_in,
                              void* d_out, int out_size)
{
    const float* x = (const float*)d_in[0];
    const float* W = (const float*)d_in[1];
    if (in_sizes[0] == (int)((size_t)IN_CAPS * NUM_CAPS * IN_DIM * OUT_DIM)) {
        const float* tmp = x; x = W; W = tmp;
    }
    float* out = (float*)d_out;

    dim3 ig(NIC, BATCH);

    // L2 ping-pong: uhat ascending-i; alternate direction each pass so every
    // pass starts on the L2-resident tail of the previous one.
    uhat_kernel<<<IN_CAPS, 512>>>(x, W);

    iter_kernel<<<ig, 256>>>(0, 1);          // reverse
    squash_kernel<<<BATCH, 512>>>(0, out);   // -> g_out0

    iter_kernel<<<ig, 256>>>(1, 0);          // forward
    squash_kernel<<<BATCH, 512>>>(1, out);   // -> g_out1

    iter_kernel<<<ig, 256>>>(2, 1);          // reverse
    squash_kernel<<<BATCH, 512>>>(2, out);   // -> dout
}